// round 7
// baseline (speedup 1.0000x reference)
#include <cuda_runtime.h>
#include <cstdint>
#include <math.h>

#define LSEQ 4096
#define HDIM 512

// ---------------- scratch (__device__ globals; no allocation allowed) ----------------
__device__ float d_gi[2][(size_t)LSEQ * 1536];     // precomputed input gates, per dir
__device__ float d_hstate[2][2][HDIM];             // parity double-buffered h data
__device__ unsigned long long d_hflag[2][2][32][16]; // per-producer flags, 128B stride
__device__ float d_outcat[(size_t)LSEQ * 1024];    // [out_f | out_b]
__device__ float d_U1[(size_t)LSEQ * 9216];
__device__ float d_V1[(size_t)HDIM * 9216];
__device__ float d_U2[(size_t)LSEQ * 4608];
__device__ float d_V2[(size_t)HDIM * 4608];
__device__ float d_a2[(size_t)LSEQ * HDIM];

// ---------------- init ----------------
__global__ void init_kernel() {
    int t = blockIdx.x * blockDim.x + threadIdx.x;
    if (t < 2 * 2 * 32 * 16) ((unsigned long long*)d_hflag)[t] = 0ull;
    if (t < 2 * 2 * HDIM) ((float*)d_hstate)[t] = 0.f;
}

// ---------------- packed f32x2 helpers ----------------
__device__ __forceinline__ unsigned long long pack2f(float x, float y) {
    unsigned long long r;
    asm("mov.b64 %0, {%1, %2};" : "=l"(r) : "f"(x), "f"(y));
    return r;
}
__device__ __forceinline__ void unpack2f(unsigned long long v, float& x, float& y) {
    asm("mov.b64 {%0, %1}, %2;" : "=f"(x), "=f"(y) : "l"(v));
}
#define FMA2(d, a, b) asm("fma.rn.f32x2 %0, %1, %2, %0;" : "+l"(d) : "l"(a), "l"(b))

// ---------------- SGEMM (R2 f32x2 diagonal version, correctness-proven) ----------------
// C[M,N] = act(A[M,K] @ B[N,K]^T + bias[N]); 128x128 block, BK=16, 256 thr, 8x8/thread
__global__ __launch_bounds__(256, 2) void sgemm_kernel(
    const float* __restrict__ A, const float* __restrict__ B,
    const float* __restrict__ bias, float* __restrict__ C,
    int M, int N, int K, int act)
{
    __shared__ float As[16][128];
    __shared__ float Bs[16][128];
    __shared__ float Bw[16][128];   // pair-swapped copy of Bs along n
    int tid = threadIdx.x;
    int tx = tid & 15, ty = tid >> 4;
    const float* Ablk = A + (size_t)blockIdx.y * 128 * K;
    const float* Bblk = B + (size_t)blockIdx.x * 128 * K;

    int r0 = tid >> 2;
    int c0 = (tid & 3) * 4;

    unsigned long long P[4][4], Q[4][4];
    unsigned long long zz = pack2f(0.f, 0.f);
#pragma unroll
    for (int i = 0; i < 4; i++)
#pragma unroll
        for (int j = 0; j < 4; j++) { P[i][j] = zz; Q[i][j] = zz; }

    float4 pa0 = *(const float4*)(Ablk + (size_t)r0 * K + c0);
    float4 pa1 = *(const float4*)(Ablk + (size_t)(r0 + 64) * K + c0);
    float4 pb0 = *(const float4*)(Bblk + (size_t)r0 * K + c0);
    float4 pb1 = *(const float4*)(Bblk + (size_t)(r0 + 64) * K + c0);

    for (int k0 = 0; k0 < K; k0 += 16) {
        As[c0 + 0][r0] = pa0.x; As[c0 + 1][r0] = pa0.y; As[c0 + 2][r0] = pa0.z; As[c0 + 3][r0] = pa0.w;
        As[c0 + 0][r0 + 64] = pa1.x; As[c0 + 1][r0 + 64] = pa1.y; As[c0 + 2][r0 + 64] = pa1.z; As[c0 + 3][r0 + 64] = pa1.w;
        Bs[c0 + 0][r0] = pb0.x; Bs[c0 + 1][r0] = pb0.y; Bs[c0 + 2][r0] = pb0.z; Bs[c0 + 3][r0] = pb0.w;
        Bs[c0 + 0][r0 + 64] = pb1.x; Bs[c0 + 1][r0 + 64] = pb1.y; Bs[c0 + 2][r0 + 64] = pb1.z; Bs[c0 + 3][r0 + 64] = pb1.w;
        int rs0 = r0 ^ 1, rs1 = (r0 + 64) ^ 1;
        Bw[c0 + 0][rs0] = pb0.x; Bw[c0 + 1][rs0] = pb0.y; Bw[c0 + 2][rs0] = pb0.z; Bw[c0 + 3][rs0] = pb0.w;
        Bw[c0 + 0][rs1] = pb1.x; Bw[c0 + 1][rs1] = pb1.y; Bw[c0 + 2][rs1] = pb1.z; Bw[c0 + 3][rs1] = pb1.w;
        __syncthreads();

        if (k0 + 16 < K) {
            pa0 = *(const float4*)(Ablk + (size_t)r0 * K + k0 + 16 + c0);
            pa1 = *(const float4*)(Ablk + (size_t)(r0 + 64) * K + k0 + 16 + c0);
            pb0 = *(const float4*)(Bblk + (size_t)r0 * K + k0 + 16 + c0);
            pb1 = *(const float4*)(Bblk + (size_t)(r0 + 64) * K + k0 + 16 + c0);
        }

#pragma unroll
        for (int k = 0; k < 16; k++) {
            float4 av0 = *(const float4*)&As[k][ty * 8];
            float4 av1 = *(const float4*)&As[k][ty * 8 + 4];
            float4 bv0 = *(const float4*)&Bs[k][tx * 8];
            float4 bv1 = *(const float4*)&Bs[k][tx * 8 + 4];
            float4 wv0 = *(const float4*)&Bw[k][tx * 8];
            float4 wv1 = *(const float4*)&Bw[k][tx * 8 + 4];
            unsigned long long ap[4], bp[4], wp[4];
            ap[0] = pack2f(av0.x, av0.y); ap[1] = pack2f(av0.z, av0.w);
            ap[2] = pack2f(av1.x, av1.y); ap[3] = pack2f(av1.z, av1.w);
            bp[0] = pack2f(bv0.x, bv0.y); bp[1] = pack2f(bv0.z, bv0.w);
            bp[2] = pack2f(bv1.x, bv1.y); bp[3] = pack2f(bv1.z, bv1.w);
            wp[0] = pack2f(wv0.x, wv0.y); wp[1] = pack2f(wv0.z, wv0.w);
            wp[2] = pack2f(wv1.x, wv1.y); wp[3] = pack2f(wv1.z, wv1.w);
#pragma unroll
            for (int ii = 0; ii < 4; ii++)
#pragma unroll
                for (int jj = 0; jj < 4; jj++) {
                    FMA2(P[ii][jj], ap[ii], bp[jj]);
                    FMA2(Q[ii][jj], ap[ii], wp[jj]);
                }
        }
        __syncthreads();
    }

    float acc[8][8];
#pragma unroll
    for (int ii = 0; ii < 4; ii++)
#pragma unroll
        for (int jj = 0; jj < 4; jj++) {
            float px, py, qx, qy;
            unpack2f(P[ii][jj], px, py);
            unpack2f(Q[ii][jj], qx, qy);
            acc[2 * ii][2 * jj] = px;
            acc[2 * ii + 1][2 * jj + 1] = py;
            acc[2 * ii][2 * jj + 1] = qx;
            acc[2 * ii + 1][2 * jj] = qy;
        }

    int nbase = blockIdx.x * 128 + tx * 8;
    int mbase = blockIdx.y * 128 + ty * 8;
#pragma unroll
    for (int i = 0; i < 8; i++) {
#pragma unroll
        for (int j = 0; j < 8; j++) {
            float v = acc[i][j];
            if (bias) v += bias[nbase + j];
            if (act == 1) v = fmaxf(v, 0.f);
            else if (act == 2) v = 1.f / (1.f + expf(-v));
            acc[i][j] = v;
        }
        float4* dst = (float4*)(C + (size_t)(mbase + i) * N + nbase);
        dst[0] = make_float4(acc[i][0], acc[i][1], acc[i][2], acc[i][3]);
        dst[1] = make_float4(acc[i][4], acc[i][5], acc[i][6], acc[i][7]);
    }
}

// ---------------- persistent bidirectional GRU recurrence (v4) ----------------
// 32 CTAs/dir (64 total). Each CTA owns 16 outputs -> 48 dots of len 512,
// 8 lanes/dot, weights as f32x2 in registers (32 FMA2/thread).
// Exchange: 16 gate threads st.relaxed their float into the parity slot,
// syncwarp, tid0 release-stores the flag. Consumers: 31 staggered pollers,
// one flag each; on success load that producer's 64B into smem. 2 bars/step.
#define GCTAS 32
#define GOUT 16
#define GTH 384

__global__ __launch_bounds__(GTH, 1) void gru_kernel(
    const float* __restrict__ whh_f, const float* __restrict__ bhh_f,
    const float* __restrict__ whh_b, const float* __restrict__ bhh_b)
{
    int cta = blockIdx.x;
    int dir = (cta >= GCTAS) ? 1 : 0;
    int slice = cta - dir * GCTAS;
    const float* whh = dir ? whh_b : whh_f;
    const float* bhh = dir ? bhh_b : bhh_f;
    const float* gibase = d_gi[dir];

    int tid = threadIdx.x;
    int dot = tid >> 3;            // 0..47
    int lane = tid & 7;            // 0..7, handles h[lane*64 .. lane*64+64)
    int gate = dot >> 4;           // 0..2
    int jl = dot & 15;             // 0..15
    int jg = slice * GOUT + jl;    // global output index

    // packed weights: 64 floats -> 32 f32x2 words per thread (48KB/CTA)
    unsigned long long w2[32];
    {
        const unsigned long long* wr =
            (const unsigned long long*)(whh + (size_t)(gate * HDIM + jg) * HDIM + lane * 64);
#pragma unroll
        for (int i = 0; i < 32; i++) w2[i] = wr[i];
    }
    float myb = bhh[gate * HDIM + jg];

    __shared__ __align__(16) float h_sh[HDIM];
    __shared__ float s_sum[48];
    __shared__ float s_gi[48];

    for (int i = tid; i < HDIM; i += GTH) h_sh[i] = 0.f;
    float hprev = 0.f;             // valid for tid < GOUT
    __syncthreads();

    for (int s = 0; s < LSEQ; s++) {
        int t = dir ? (LSEQ - 1 - s) : s;

        // gi prefetch by dot leaders — independent of the flag wait
        float giv = 0.f;
        if (lane == 0) giv = __ldg(gibase + (size_t)t * 1536 + gate * HDIM + jg);

        // (A) poll flags + fetch peer h slots (warp 2: 31 staggered pollers)
        if (s > 0 && tid >= 64 && tid < 96) {
            int i = tid - 64;
            int g = (slice + 1 + i) & 31;
            if (g != slice) {
                const unsigned long long* flg = &d_hflag[dir][s & 1][g][0];
                unsigned long long tg;
                do {
                    asm volatile("ld.acquire.gpu.global.b64 %0, [%1];"
                                 : "=l"(tg) : "l"(flg) : "memory");
                } while ((unsigned)tg != (unsigned)s);
                const float4* src = ((const float4*)d_hstate[dir][s & 1]) + g * 4;
                float4 v0 = __ldcg(src);
                float4 v1 = __ldcg(src + 1);
                float4 v2 = __ldcg(src + 2);
                float4 v3 = __ldcg(src + 3);
                float4* dst = ((float4*)h_sh) + g * 4;
                dst[0] = v0; dst[1] = v1; dst[2] = v2; dst[3] = v3;
            }
        }
        __syncthreads();   // (B)

        // (C) partial dot over 64 h values (f32x2)
        unsigned long long acc2 = 0ull;
        const ulonglong2* hv2 = ((const ulonglong2*)h_sh) + lane * 16;
#pragma unroll
        for (int i = 0; i < 16; i++) {
            ulonglong2 hv = hv2[i];
            FMA2(acc2, w2[2 * i], hv.x);
            FMA2(acc2, w2[2 * i + 1], hv.y);
        }
        float ax, ay;
        unpack2f(acc2, ax, ay);
        float acc = ax + ay;
        acc += __shfl_down_sync(0xffffffffu, acc, 4, 8);
        acc += __shfl_down_sync(0xffffffffu, acc, 2, 8);
        acc += __shfl_down_sync(0xffffffffu, acc, 1, 8);
        if (lane == 0) { s_sum[dot] = acc + myb; s_gi[dot] = giv; }
        __syncthreads();   // (D)

        // (E) gates + publish (16 threads of warp 0)
        if (tid < GOUT) {
            float r = 1.f / (1.f + __expf(-(s_gi[tid] + s_sum[tid])));
            float z = 1.f / (1.f + __expf(-(s_gi[16 + tid] + s_sum[16 + tid])));
            float x = s_gi[32 + tid] + r * s_sum[32 + tid];
            float e = __expf(2.f * x);
            float n = 1.f - 2.f / (e + 1.f);          // tanh(x)
            float hnew = (1.f - z) * n + z * hprev;
            hprev = hnew;
            h_sh[slice * GOUT + tid] = hnew;          // own slice locally
            d_outcat[(size_t)t * 1024 + dir * HDIM + slice * GOUT + tid] = hnew;
            // parallel data publish into parity-(s+1) slot
            float* dslot = &d_hstate[dir][(s + 1) & 1][slice * GOUT + tid];
            asm volatile("st.relaxed.gpu.global.f32 [%0], %1;" :: "l"(dslot), "f"(hnew) : "memory");
            __syncwarp(0x0000ffffu);
            if (tid == 0) {
                unsigned long long tagv = (unsigned long long)(unsigned)(s + 1);
                asm volatile("st.release.gpu.global.b64 [%0], %1;"
                             :: "l"(&d_hflag[dir][(s + 1) & 1][slice][0]), "l"(tagv) : "memory");
            }
        }
        // (A)-next (pollers, other slices' h_sh) is separated from (C) reads by (D);
        // (E) own-slice h_sh write is separated from (C)-next by (B)-next.
    }
}

// ---------------- KAN prep: cubic B-spline basis on efficient-kan extended grid ----------------
__device__ __forceinline__ void bspline8(float x, float* bs) {
    const float hstep = 2.0f / 5.0f;
    float g[12];
#pragma unroll
    for (int m = 0; m < 12; m++) g[m] = (float)(m - 3) * hstep - 1.0f;
    float b[11];
#pragma unroll
    for (int m = 0; m < 11; m++) b[m] = (x >= g[m] && x < g[m + 1]) ? 1.f : 0.f;
#pragma unroll
    for (int k = 1; k <= 3; k++) {
#pragma unroll
        for (int m = 0; m < 11 - k; m++) {
            b[m] = (x - g[m]) / (g[m + k] - g[m]) * b[m]
                 + (g[m + k + 1] - x) / (g[m + k + 1] - g[m + 1]) * b[m + 1];
        }
    }
#pragma unroll
    for (int m = 0; m < 8; m++) bs[m] = b[m];
}

// U[n] = [ silu(x[n,:]) | bases(x[n,:])... ] width = 9*inw
__global__ void prep_U_kernel(const float* __restrict__ X, float* __restrict__ U, int inw) {
    int idx = blockIdx.x * blockDim.x + threadIdx.x;
    int total = LSEQ * inw;
    if (idx >= total) return;
    int n = idx / inw, i = idx - n * inw;
    float x = X[idx];
    int uw = inw * 9;
    U[(size_t)n * uw + i] = x / (1.f + expf(-x));
    float bs[8];
    bspline8(x, bs);
    float4* d4 = (float4*)(U + (size_t)n * uw + inw + (size_t)i * 8);
    d4[0] = make_float4(bs[0], bs[1], bs[2], bs[3]);
    d4[1] = make_float4(bs[4], bs[5], bs[6], bs[7]);
}

// V[o] = [ base_w[o,:] | spline_w[o,:,:]*scaler[o,:] ]
__global__ void prep_V_kernel(const float* __restrict__ bw, const float* __restrict__ sw,
                              const float* __restrict__ sc, float* __restrict__ V, int inw) {
    int idx = blockIdx.x * blockDim.x + threadIdx.x;
    int total = HDIM * inw;
    if (idx >= total) return;
    int o = idx / inw, i = idx - o * inw;
    int uw = inw * 9;
    V[(size_t)o * uw + i] = bw[idx];
    float s = sc[idx];
    const float* swp = sw + (size_t)idx * 8;
    float4* d4 = (float4*)(V + (size_t)o * uw + inw + (size_t)i * 8);
    d4[0] = make_float4(swp[0] * s, swp[1] * s, swp[2] * s, swp[3] * s);
    d4[1] = make_float4(swp[4] * s, swp[5] * s, swp[6] * s, swp[7] * s);
}

// ---------------- y[o] = sum_n a2[n,o] * p[n] ----------------
__global__ void final_kernel(const float* __restrict__ p, float* __restrict__ y) {
    __shared__ float red[256];
    int o = blockIdx.x * 64 + (threadIdx.x & 63);
    int part = threadIdx.x >> 6;
    float acc = 0.f;
    for (int n = part; n < LSEQ; n += 4)
        acc += d_a2[(size_t)n * HDIM + o] * p[n];
    red[threadIdx.x] = acc;
    __syncthreads();
    if (part == 0)
        y[o] = red[threadIdx.x] + red[threadIdx.x + 64]
             + red[threadIdx.x + 128] + red[threadIdx.x + 192];
}

// ---------------- launch ----------------
extern "C" void kernel_launch(void* const* d_in, const int* in_sizes, int n_in,
                              void* d_out, int out_size) {
    const float* h    = (const float*)d_in[0];
    const float* p    = (const float*)d_in[1];
    const float* wihf = (const float*)d_in[2];
    const float* whhf = (const float*)d_in[3];
    const float* bihf = (const float*)d_in[4];
    const float* bhhf = (const float*)d_in[5];
    const float* wihb = (const float*)d_in[6];
    const float* whhb = (const float*)d_in[7];
    const float* bihb = (const float*)d_in[8];
    const float* bhhb = (const float*)d_in[9];
    const float* bw1  = (const float*)d_in[10];
    const float* sw1  = (const float*)d_in[11];
    const float* sc1  = (const float*)d_in[12];
    const float* bw2  = (const float*)d_in[13];
    const float* sw2  = (const float*)d_in[14];
    const float* sc2  = (const float*)d_in[15];

    float* out = (float*)d_out;
    float* y  = out;           // (512,)
    float* a1 = out + 512;     // (4096, 512)

    float *gi0, *oc, *u1, *v1, *u2, *v2, *a2;
    cudaGetSymbolAddress((void**)&gi0, d_gi);
    cudaGetSymbolAddress((void**)&oc,  d_outcat);
    cudaGetSymbolAddress((void**)&u1,  d_U1);
    cudaGetSymbolAddress((void**)&v1,  d_V1);
    cudaGetSymbolAddress((void**)&u2,  d_U2);
    cudaGetSymbolAddress((void**)&v2,  d_V2);
    cudaGetSymbolAddress((void**)&a2,  d_a2);
    float* gi1 = gi0 + (size_t)LSEQ * 1536;

    init_kernel<<<2, 1024>>>();

    // input-gate GEMMs: gi = h @ w_ih^T + b_ih   (4096 x 1536, K=512)
    sgemm_kernel<<<dim3(1536 / 128, LSEQ / 128), 256>>>(h, wihf, bihf, gi0, LSEQ, 1536, 512, 0);
    sgemm_kernel<<<dim3(1536 / 128, LSEQ / 128), 256>>>(h, wihb, bihb, gi1, LSEQ, 1536, 512, 0);

    // persistent bidirectional recurrence
    gru_kernel<<<2 * GCTAS, GTH>>>(whhf, bhhf, whhb, bhhb);

    // KAN layer 1: a1 = relu(U1 @ V1^T), U1 = [silu | bases] of outcat (width 9216)
    prep_V_kernel<<<(HDIM * 1024 + 255) / 256, 256>>>(bw1, sw1, sc1, v1, 1024);
    prep_U_kernel<<<(LSEQ * 1024 + 255) / 256, 256>>>(oc, u1, 1024);
    sgemm_kernel<<<dim3(HDIM / 128, LSEQ / 128), 256>>>(u1, v1, nullptr, a1, LSEQ, HDIM, 9216, 1);

    // KAN layer 2: a2 = sigmoid(U2 @ V2^T), width 4608
    prep_V_kernel<<<(HDIM * 512 + 255) / 256, 256>>>(bw2, sw2, sc2, v2, 512);
    prep_U_kernel<<<(LSEQ * 512 + 255) / 256, 256>>>(a1, u2, 512);
    sgemm_kernel<<<dim3(HDIM / 128, LSEQ / 128), 256>>>(u2, v2, nullptr, a2, LSEQ, HDIM, 4608, 2);

    // y = a2^T @ p
    final_kernel<<<8, 256>>>(p, y);
}

// round 8
// speedup vs baseline: 1.0767x; 1.0767x over previous
#include <cuda_runtime.h>
#include <cstdint>
#include <math.h>

#define LSEQ 4096
#define HDIM 512

// ---------------- scratch (__device__ globals; no allocation allowed) ----------------
__device__ float d_gi[2][(size_t)LSEQ * 1536];     // precomputed input gates, per dir
__device__ float d_hstate[2][2][HDIM];             // parity double-buffered h data
__device__ unsigned int d_ctr[4][32];              // [dir*2+group] counters, 128B apart
__device__ float d_outcat[(size_t)LSEQ * 1024];    // [out_f | out_b]
__device__ float d_U1[(size_t)LSEQ * 9216];
__device__ float d_V1[(size_t)HDIM * 9216];
__device__ float d_U2[(size_t)LSEQ * 4608];
__device__ float d_V2[(size_t)HDIM * 4608];
__device__ float d_a2[(size_t)LSEQ * HDIM];

// ---------------- init ----------------
__global__ void init_kernel() {
    int t = blockIdx.x * blockDim.x + threadIdx.x;
    if (t < 4 * 32) ((unsigned int*)d_ctr)[t] = 0u;
    if (t < 2 * 2 * HDIM) ((float*)d_hstate)[t] = 0.f;
}

// ---------------- packed f32x2 helpers ----------------
__device__ __forceinline__ unsigned long long pack2f(float x, float y) {
    unsigned long long r;
    asm("mov.b64 %0, {%1, %2};" : "=l"(r) : "f"(x), "f"(y));
    return r;
}
__device__ __forceinline__ void unpack2f(unsigned long long v, float& x, float& y) {
    asm("mov.b64 {%0, %1}, %2;" : "=f"(x), "=f"(y) : "l"(v));
}
#define FMA2(d, a, b) asm("fma.rn.f32x2 %0, %1, %2, %0;" : "+l"(d) : "l"(a), "l"(b))

// ---------------- SGEMM (R1 version, proven in the 10.98ms run) ----------------
// C[M,N] = act(A[M,K] @ B[N,K]^T + bias[N]); 128x128 block, BK=16, 256 thr, 8x8/thread
__global__ __launch_bounds__(256) void sgemm_kernel(
    const float* __restrict__ A, const float* __restrict__ B,
    const float* __restrict__ bias, float* __restrict__ C,
    int M, int N, int K, int act)
{
    __shared__ float As[16][128];
    __shared__ float Bs[16][128];
    int tid = threadIdx.x;
    int tx = tid % 16, ty = tid / 16;
    const float* Ablk = A + (size_t)blockIdx.y * 128 * K;
    const float* Bblk = B + (size_t)blockIdx.x * 128 * K;

    float acc[8][8];
#pragma unroll
    for (int i = 0; i < 8; i++)
#pragma unroll
        for (int j = 0; j < 8; j++) acc[i][j] = 0.f;

    for (int k0 = 0; k0 < K; k0 += 16) {
#pragma unroll
        for (int i = 0; i < 2; i++) {
            int idx = tid + i * 256;
            int r = idx >> 2;
            int c4 = idx & 3;
            float4 va = *(const float4*)(Ablk + (size_t)r * K + k0 + c4 * 4);
            As[c4 * 4 + 0][r] = va.x; As[c4 * 4 + 1][r] = va.y;
            As[c4 * 4 + 2][r] = va.z; As[c4 * 4 + 3][r] = va.w;
            float4 vb = *(const float4*)(Bblk + (size_t)r * K + k0 + c4 * 4);
            Bs[c4 * 4 + 0][r] = vb.x; Bs[c4 * 4 + 1][r] = vb.y;
            Bs[c4 * 4 + 2][r] = vb.z; Bs[c4 * 4 + 3][r] = vb.w;
        }
        __syncthreads();
#pragma unroll
        for (int k = 0; k < 16; k++) {
            float4 a0 = *(const float4*)&As[k][ty * 8];
            float4 a1 = *(const float4*)&As[k][ty * 8 + 4];
            float4 b0 = *(const float4*)&Bs[k][tx * 8];
            float4 b1 = *(const float4*)&Bs[k][tx * 8 + 4];
            float ar[8] = {a0.x, a0.y, a0.z, a0.w, a1.x, a1.y, a1.z, a1.w};
            float br[8] = {b0.x, b0.y, b0.z, b0.w, b1.x, b1.y, b1.z, b1.w};
#pragma unroll
            for (int i = 0; i < 8; i++)
#pragma unroll
                for (int j = 0; j < 8; j++) acc[i][j] = fmaf(ar[i], br[j], acc[i][j]);
        }
        __syncthreads();
    }

    int nbase = blockIdx.x * 128 + tx * 8;
    int mbase = blockIdx.y * 128 + ty * 8;
#pragma unroll
    for (int i = 0; i < 8; i++) {
#pragma unroll
        for (int j = 0; j < 8; j++) {
            float v = acc[i][j];
            if (bias) v += bias[nbase + j];
            if (act == 1) v = fmaxf(v, 0.f);
            else if (act == 2) v = 1.f / (1.f + expf(-v));
            acc[i][j] = v;
        }
        float4* dst = (float4*)(C + (size_t)(mbase + i) * N + nbase);
        dst[0] = make_float4(acc[i][0], acc[i][1], acc[i][2], acc[i][3]);
        dst[1] = make_float4(acc[i][4], acc[i][5], acc[i][6], acc[i][7]);
    }
}

// ---------------- persistent bidirectional GRU recurrence (v5 = R1 topology, tuned) ----------------
// 32 CTAs/dir. Each CTA owns 16 outputs -> 48 dots of len 512, 8 lanes/dot,
// weights register-resident as f32x2 (32 FMA2/thread). Barrier: split release-
// reduction counters (2 groups of 16 CTAs per dir), tid0/tid1 poll in parallel.
// h exchange: 16 parallel st.relaxed publishes; bulk 128-thread __ldcg reload.
#define GCTAS 32
#define GOUT 16
#define GTH 384

__global__ __launch_bounds__(GTH, 1) void gru_kernel(
    const float* __restrict__ whh_f, const float* __restrict__ bhh_f,
    const float* __restrict__ whh_b, const float* __restrict__ bhh_b)
{
    int cta = blockIdx.x;
    int dir = (cta >= GCTAS) ? 1 : 0;
    int slice = cta - dir * GCTAS;
    const float* whh = dir ? whh_b : whh_f;
    const float* bhh = dir ? bhh_b : bhh_f;
    const float* gibase = d_gi[dir];

    int tid = threadIdx.x;
    int dot = tid >> 3;            // 0..47
    int lane = tid & 7;            // 0..7, covers h[lane*64 .. lane*64+64)
    int gate = dot >> 4;           // 0..2
    int jl = dot & 15;             // 0..15
    int jg = slice * GOUT + jl;

    // register weights: 64 floats = 32 f32x2 words per thread
    unsigned long long w2[32];
    {
        const unsigned long long* wr =
            (const unsigned long long*)(whh + (size_t)(gate * HDIM + jg) * HDIM + lane * 64);
#pragma unroll
        for (int i = 0; i < 32; i++) w2[i] = wr[i];
    }
    float myb = bhh[gate * HDIM + jg];

    unsigned int* myctr  = &d_ctr[dir * 2 + (slice >> 4)][0];
    unsigned int* ctrs   = &d_ctr[dir * 2][0];   // group counters at stride 32

    __shared__ __align__(16) float h_sh[HDIM];
    __shared__ float s_sum[48];
    __shared__ float s_gi[48];

    for (int i = tid; i < HDIM; i += GTH) h_sh[i] = 0.f;
    float hprev = 0.f;             // valid for tid < GOUT
    __syncthreads();

    for (int s = 0; s < LSEQ; s++) {
        int t = dir ? (LSEQ - 1 - s) : s;

        // gi prefetch by dot leaders (overlaps the h reload)
        float giv = 0.f;
        if (lane == 0) giv = __ldg(gibase + (size_t)t * 1536 + gate * HDIM + jg);

        // (A) bulk h reload: one coalesced 128 x float4 wave
        if (s > 0 && tid < 128)
            ((float4*)h_sh)[tid] = __ldcg(((const float4*)d_hstate[dir][s & 1]) + tid);
        __syncthreads();   // (B)

        // (C) dot: 64 h values per thread via f32x2, 8-lane shfl reduce
        unsigned long long acc2 = 0ull;
        const ulonglong2* hv2 = ((const ulonglong2*)h_sh) + lane * 16;
#pragma unroll
        for (int i = 0; i < 16; i++) {
            ulonglong2 hv = hv2[i];
            FMA2(acc2, w2[2 * i], hv.x);
            FMA2(acc2, w2[2 * i + 1], hv.y);
        }
        float ax, ay;
        unpack2f(acc2, ax, ay);
        float acc = ax + ay;
        acc += __shfl_down_sync(0xffffffffu, acc, 4, 8);
        acc += __shfl_down_sync(0xffffffffu, acc, 2, 8);
        acc += __shfl_down_sync(0xffffffffu, acc, 1, 8);
        if (lane == 0) { s_sum[dot] = acc + myb; s_gi[dot] = giv; }
        __syncthreads();   // (D)

        // (E) gates + publish + barrier arrive (warp 0, 16 threads)
        if (tid < GOUT) {
            float r = 1.f / (1.f + __expf(-(s_gi[tid] + s_sum[tid])));
            float z = 1.f / (1.f + __expf(-(s_gi[16 + tid] + s_sum[16 + tid])));
            float x = s_gi[32 + tid] + r * s_sum[32 + tid];
            float e = __expf(2.f * x);
            float n = 1.f - 2.f / (e + 1.f);          // tanh(x)
            float hnew = (1.f - z) * n + z * hprev;
            hprev = hnew;
            d_outcat[(size_t)t * 1024 + dir * HDIM + slice * GOUT + tid] = hnew;
            float* dslot = &d_hstate[dir][(s + 1) & 1][slice * GOUT + tid];
            asm volatile("st.relaxed.gpu.global.f32 [%0], %1;" :: "l"(dslot), "f"(hnew) : "memory");
            __syncwarp(0x0000ffffu);
            if (tid == 0)
                asm volatile("red.release.gpu.global.add.u32 [%0], %1;"
                             :: "l"(myctr), "r"(1u) : "memory");
        }

        // (F) barrier wait: tid0 polls group0 counter, tid1 polls group1
        if (s + 1 < LSEQ) {
            if (tid < 2) {
                unsigned int target = (unsigned)(s + 1) * 16u;
                const unsigned int* c = ctrs + tid * 32;
                unsigned int v;
                do {
                    asm volatile("ld.acquire.gpu.global.u32 %0, [%1];"
                                 : "=r"(v) : "l"(c) : "memory");
                } while (v < target);
            }
            __syncthreads();   // (G)
        }
    }
}

// ---------------- KAN prep: cubic B-spline basis on efficient-kan extended grid ----------------
__device__ __forceinline__ void bspline8(float x, float* bs) {
    const float hstep = 2.0f / 5.0f;
    float g[12];
#pragma unroll
    for (int m = 0; m < 12; m++) g[m] = (float)(m - 3) * hstep - 1.0f;
    float b[11];
#pragma unroll
    for (int m = 0; m < 11; m++) b[m] = (x >= g[m] && x < g[m + 1]) ? 1.f : 0.f;
#pragma unroll
    for (int k = 1; k <= 3; k++) {
#pragma unroll
        for (int m = 0; m < 11 - k; m++) {
            b[m] = (x - g[m]) / (g[m + k] - g[m]) * b[m]
                 + (g[m + k + 1] - x) / (g[m + k + 1] - g[m + 1]) * b[m + 1];
        }
    }
#pragma unroll
    for (int m = 0; m < 8; m++) bs[m] = b[m];
}

// U[n] = [ silu(x[n,:]) | bases(x[n,:])... ] width = 9*inw
__global__ void prep_U_kernel(const float* __restrict__ X, float* __restrict__ U, int inw) {
    int idx = blockIdx.x * blockDim.x + threadIdx.x;
    int total = LSEQ * inw;
    if (idx >= total) return;
    int n = idx / inw, i = idx - n * inw;
    float x = X[idx];
    int uw = inw * 9;
    U[(size_t)n * uw + i] = x / (1.f + expf(-x));
    float bs[8];
    bspline8(x, bs);
    float4* d4 = (float4*)(U + (size_t)n * uw + inw + (size_t)i * 8);
    d4[0] = make_float4(bs[0], bs[1], bs[2], bs[3]);
    d4[1] = make_float4(bs[4], bs[5], bs[6], bs[7]);
}

// V[o] = [ base_w[o,:] | spline_w[o,:,:]*scaler[o,:] ]
__global__ void prep_V_kernel(const float* __restrict__ bw, const float* __restrict__ sw,
                              const float* __restrict__ sc, float* __restrict__ V, int inw) {
    int idx = blockIdx.x * blockDim.x + threadIdx.x;
    int total = HDIM * inw;
    if (idx >= total) return;
    int o = idx / inw, i = idx - o * inw;
    int uw = inw * 9;
    V[(size_t)o * uw + i] = bw[idx];
    float s = sc[idx];
    const float* swp = sw + (size_t)idx * 8;
    float4* d4 = (float4*)(V + (size_t)o * uw + inw + (size_t)i * 8);
    d4[0] = make_float4(swp[0] * s, swp[1] * s, swp[2] * s, swp[3] * s);
    d4[1] = make_float4(swp[4] * s, swp[5] * s, swp[6] * s, swp[7] * s);
}

// ---------------- y[o] = sum_n a2[n,o] * p[n] ----------------
__global__ void final_kernel(const float* __restrict__ p, float* __restrict__ y) {
    __shared__ float red[256];
    int o = blockIdx.x * 64 + (threadIdx.x & 63);
    int part = threadIdx.x >> 6;
    float acc = 0.f;
    for (int n = part; n < LSEQ; n += 4)
        acc += d_a2[(size_t)n * HDIM + o] * p[n];
    red[threadIdx.x] = acc;
    __syncthreads();
    if (part == 0)
        y[o] = red[threadIdx.x] + red[threadIdx.x + 64]
             + red[threadIdx.x + 128] + red[threadIdx.x + 192];
}

// ---------------- launch ----------------
extern "C" void kernel_launch(void* const* d_in, const int* in_sizes, int n_in,
                              void* d_out, int out_size) {
    const float* h    = (const float*)d_in[0];
    const float* p    = (const float*)d_in[1];
    const float* wihf = (const float*)d_in[2];
    const float* whhf = (const float*)d_in[3];
    const float* bihf = (const float*)d_in[4];
    const float* bhhf = (const float*)d_in[5];
    const float* wihb = (const float*)d_in[6];
    const float* whhb = (const float*)d_in[7];
    const float* bihb = (const float*)d_in[8];
    const float* bhhb = (const float*)d_in[9];
    const float* bw1  = (const float*)d_in[10];
    const float* sw1  = (const float*)d_in[11];
    const float* sc1  = (const float*)d_in[12];
    const float* bw2  = (const float*)d_in[13];
    const float* sw2  = (const float*)d_in[14];
    const float* sc2  = (const float*)d_in[15];

    float* out = (float*)d_out;
    float* y  = out;           // (512,)
    float* a1 = out + 512;     // (4096, 512)

    float *gi0, *oc, *u1, *v1, *u2, *v2, *a2;
    cudaGetSymbolAddress((void**)&gi0, d_gi);
    cudaGetSymbolAddress((void**)&oc,  d_outcat);
    cudaGetSymbolAddress((void**)&u1,  d_U1);
    cudaGetSymbolAddress((void**)&v1,  d_V1);
    cudaGetSymbolAddress((void**)&u2,  d_U2);
    cudaGetSymbolAddress((void**)&v2,  d_V2);
    cudaGetSymbolAddress((void**)&a2,  d_a2);
    float* gi1 = gi0 + (size_t)LSEQ * 1536;

    init_kernel<<<2, 1024>>>();

    // input-gate GEMMs: gi = h @ w_ih^T + b_ih   (4096 x 1536, K=512)
    sgemm_kernel<<<dim3(1536 / 128, LSEQ / 128), 256>>>(h, wihf, bihf, gi0, LSEQ, 1536, 512, 0);
    sgemm_kernel<<<dim3(1536 / 128, LSEQ / 128), 256>>>(h, wihb, bihb, gi1, LSEQ, 1536, 512, 0);

    // persistent bidirectional recurrence
    gru_kernel<<<2 * GCTAS, GTH>>>(whhf, bhhf, whhb, bhhb);

    // KAN layer 1: a1 = relu(U1 @ V1^T), U1 = [silu | bases] of outcat (width 9216)
    prep_V_kernel<<<(HDIM * 1024 + 255) / 256, 256>>>(bw1, sw1, sc1, v1, 1024);
    prep_U_kernel<<<(LSEQ * 1024 + 255) / 256, 256>>>(oc, u1, 1024);
    sgemm_kernel<<<dim3(HDIM / 128, LSEQ / 128), 256>>>(u1, v1, nullptr, a1, LSEQ, HDIM, 9216, 1);

    // KAN layer 2: a2 = sigmoid(U2 @ V2^T), width 4608
    prep_V_kernel<<<(HDIM * 512 + 255) / 256, 256>>>(bw2, sw2, sc2, v2, 512);
    prep_U_kernel<<<(LSEQ * 512 + 255) / 256, 256>>>(a1, u2, 512);
    sgemm_kernel<<<dim3(HDIM / 128, LSEQ / 128), 256>>>(u2, v2, nullptr, a2, LSEQ, HDIM, 4608, 2);

    // y = a2^T @ p
    final_kernel<<<8, 256>>>(p, y);
}

// round 10
// speedup vs baseline: 2.1377x; 1.9854x over previous
#include <cuda_runtime.h>
#include <cstdint>
#include <math.h>

#define LSEQ 4096
#define HDIM 512

// ---------------- scratch (__device__ globals; no allocation allowed) ----------------
__device__ float d_gi[2][(size_t)LSEQ * 1536];     // precomputed input gates, per dir
__device__ float d_hstate[2][2][HDIM];             // parity double-buffered h data
__device__ unsigned int d_ctr[4][32];              // [dir*2+group] counters, 128B apart
__device__ float d_outcat[(size_t)LSEQ * 1024];    // [out_f | out_b]
__device__ float d_U1[(size_t)LSEQ * 9216];
__device__ float d_V1[(size_t)HDIM * 9216];
__device__ float d_U2[(size_t)LSEQ * 4608];
__device__ float d_V2[(size_t)HDIM * 4608];
__device__ float d_a2[(size_t)LSEQ * HDIM];

// ---------------- init ----------------
__global__ void init_kernel() {
    int t = blockIdx.x * blockDim.x + threadIdx.x;
    if (t < 4 * 32) ((unsigned int*)d_ctr)[t] = 0u;
    if (t < 2 * 2 * HDIM) ((float*)d_hstate)[t] = 0.f;
}

// ---------------- packed f32x2 helpers ----------------
__device__ __forceinline__ unsigned long long pack2f(float x, float y) {
    unsigned long long r;
    asm("mov.b64 %0, {%1, %2};" : "=l"(r) : "f"(x), "f"(y));
    return r;
}
__device__ __forceinline__ void unpack2f(unsigned long long v, float& x, float& y) {
    asm("mov.b64 {%0, %1}, %2;" : "=f"(x), "=f"(y) : "l"(v));
}
#define FMA2(d, a, b) asm("fma.rn.f32x2 %0, %1, %2, %0;" : "+l"(d) : "l"(a), "l"(b))

// ---------------- SGEMM (R1 version, proven in the 10.98ms run) ----------------
// C[M,N] = act(A[M,K] @ B[N,K]^T + bias[N]); 128x128 block, BK=16, 256 thr, 8x8/thread
__global__ __launch_bounds__(256) void sgemm_kernel(
    const float* __restrict__ A, const float* __restrict__ B,
    const float* __restrict__ bias, float* __restrict__ C,
    int M, int N, int K, int act)
{
    __shared__ float As[16][128];
    __shared__ float Bs[16][128];
    int tid = threadIdx.x;
    int tx = tid % 16, ty = tid / 16;
    const float* Ablk = A + (size_t)blockIdx.y * 128 * K;
    const float* Bblk = B + (size_t)blockIdx.x * 128 * K;

    float acc[8][8];
#pragma unroll
    for (int i = 0; i < 8; i++)
#pragma unroll
        for (int j = 0; j < 8; j++) acc[i][j] = 0.f;

    for (int k0 = 0; k0 < K; k0 += 16) {
#pragma unroll
        for (int i = 0; i < 2; i++) {
            int idx = tid + i * 256;
            int r = idx >> 2;
            int c4 = idx & 3;
            float4 va = *(const float4*)(Ablk + (size_t)r * K + k0 + c4 * 4);
            As[c4 * 4 + 0][r] = va.x; As[c4 * 4 + 1][r] = va.y;
            As[c4 * 4 + 2][r] = va.z; As[c4 * 4 + 3][r] = va.w;
            float4 vb = *(const float4*)(Bblk + (size_t)r * K + k0 + c4 * 4);
            Bs[c4 * 4 + 0][r] = vb.x; Bs[c4 * 4 + 1][r] = vb.y;
            Bs[c4 * 4 + 2][r] = vb.z; Bs[c4 * 4 + 3][r] = vb.w;
        }
        __syncthreads();
#pragma unroll
        for (int k = 0; k < 16; k++) {
            float4 a0 = *(const float4*)&As[k][ty * 8];
            float4 a1 = *(const float4*)&As[k][ty * 8 + 4];
            float4 b0 = *(const float4*)&Bs[k][tx * 8];
            float4 b1 = *(const float4*)&Bs[k][tx * 8 + 4];
            float ar[8] = {a0.x, a0.y, a0.z, a0.w, a1.x, a1.y, a1.z, a1.w};
            float br[8] = {b0.x, b0.y, b0.z, b0.w, b1.x, b1.y, b1.z, b1.w};
#pragma unroll
            for (int i = 0; i < 8; i++)
#pragma unroll
                for (int j = 0; j < 8; j++) acc[i][j] = fmaf(ar[i], br[j], acc[i][j]);
        }
        __syncthreads();
    }

    int nbase = blockIdx.x * 128 + tx * 8;
    int mbase = blockIdx.y * 128 + ty * 8;
#pragma unroll
    for (int i = 0; i < 8; i++) {
#pragma unroll
        for (int j = 0; j < 8; j++) {
            float v = acc[i][j];
            if (bias) v += bias[nbase + j];
            if (act == 1) v = fmaxf(v, 0.f);
            else if (act == 2) v = 1.f / (1.f + expf(-v));
            acc[i][j] = v;
        }
        float4* dst = (float4*)(C + (size_t)(mbase + i) * N + nbase);
        dst[0] = make_float4(acc[i][0], acc[i][1], acc[i][2], acc[i][3]);
        dst[1] = make_float4(acc[i][4], acc[i][5], acc[i][6], acc[i][7]);
    }
}

// ---------------- persistent bidirectional GRU recurrence (v6 = v5 + conflict-free dot) ----------------
// 32 CTAs/dir. Each CTA owns 16 outputs -> 48 dots of len 512, 8 lanes/dot.
// INTERLEAVED lane partition: lane k owns h-pairs p = k + 8*i (i=0..31), so the
// dot's smem reads are 8B words at consecutive-lane-adjacent addresses:
// conflict-free + 4-way broadcast across the warp's 4 dot groups.
#define GCTAS 32
#define GOUT 16
#define GTH 384

__global__ __launch_bounds__(GTH, 1) void gru_kernel(
    const float* __restrict__ whh_f, const float* __restrict__ bhh_f,
    const float* __restrict__ whh_b, const float* __restrict__ bhh_b)
{
    int cta = blockIdx.x;
    int dir = (cta >= GCTAS) ? 1 : 0;
    int slice = cta - dir * GCTAS;
    const float* whh = dir ? whh_b : whh_f;
    const float* bhh = dir ? bhh_b : bhh_f;
    const float* gibase = d_gi[dir];

    int tid = threadIdx.x;
    int dot = tid >> 3;            // 0..47
    int lane = tid & 7;            // 0..7, owns h pairs lane+8*i
    int gate = dot >> 4;           // 0..2
    int jl = dot & 15;             // 0..15
    int jg = slice * GOUT + jl;

    // register weights matching the interleaved h partition:
    // w2[i] = (whh[row][2*(lane+8i)], whh[row][2*(lane+8i)+1])
    unsigned long long w2[32];
    {
        const unsigned long long* wr =
            (const unsigned long long*)(whh + (size_t)(gate * HDIM + jg) * HDIM);
#pragma unroll
        for (int i = 0; i < 32; i++) w2[i] = wr[lane + 8 * i];
    }
    float myb = bhh[gate * HDIM + jg];

    unsigned int* myctr  = &d_ctr[dir * 2 + (slice >> 4)][0];
    unsigned int* ctrs   = &d_ctr[dir * 2][0];   // group counters at stride 32

    __shared__ __align__(16) float h_sh[HDIM];
    __shared__ float s_sum[48];
    __shared__ float s_gi[48];

    for (int i = tid; i < HDIM; i += GTH) h_sh[i] = 0.f;
    float hprev = 0.f;             // valid for tid < GOUT
    __syncthreads();

    for (int s = 0; s < LSEQ; s++) {
        int t = dir ? (LSEQ - 1 - s) : s;

        // gi prefetch by dot leaders (overlaps the h reload)
        float giv = 0.f;
        if (lane == 0) giv = __ldg(gibase + (size_t)t * 1536 + gate * HDIM + jg);

        // (A) bulk h reload: one coalesced 128 x float4 wave
        if (s > 0 && tid < 128)
            ((float4*)h_sh)[tid] = __ldcg(((const float4*)d_hstate[dir][s & 1]) + tid);
        __syncthreads();   // (B)

        // (C) dot: 32 x 8B conflict-free smem loads, f32x2 FMA
        unsigned long long acc2 = 0ull;
        const unsigned long long* hp = (const unsigned long long*)h_sh;
#pragma unroll
        for (int i = 0; i < 32; i++)
            FMA2(acc2, w2[i], hp[lane + 8 * i]);
        float ax, ay;
        unpack2f(acc2, ax, ay);
        float acc = ax + ay;
        acc += __shfl_down_sync(0xffffffffu, acc, 4, 8);
        acc += __shfl_down_sync(0xffffffffu, acc, 2, 8);
        acc += __shfl_down_sync(0xffffffffu, acc, 1, 8);
        if (lane == 0) { s_sum[dot] = acc + myb; s_gi[dot] = giv; }
        __syncthreads();   // (D)

        // (E) gates + publish + barrier arrive (warp 0, 16 threads)
        if (tid < GOUT) {
            float r = 1.f / (1.f + __expf(-(s_gi[tid] + s_sum[tid])));
            float z = 1.f / (1.f + __expf(-(s_gi[16 + tid] + s_sum[16 + tid])));
            float x = s_gi[32 + tid] + r * s_sum[32 + tid];
            float e = __expf(2.f * x);
            float n = 1.f - 2.f / (e + 1.f);          // tanh(x)
            float hnew = (1.f - z) * n + z * hprev;
            hprev = hnew;
            d_outcat[(size_t)t * 1024 + dir * HDIM + slice * GOUT + tid] = hnew;
            float* dslot = &d_hstate[dir][(s + 1) & 1][slice * GOUT + tid];
            asm volatile("st.relaxed.gpu.global.f32 [%0], %1;" :: "l"(dslot), "f"(hnew) : "memory");
            __syncwarp(0x0000ffffu);
            if (tid == 0)
                asm volatile("red.release.gpu.global.add.u32 [%0], %1;"
                             :: "l"(myctr), "r"(1u) : "memory");
        }

        // (F) barrier wait: tid0 polls group0 counter, tid1 polls group1
        if (s + 1 < LSEQ) {
            if (tid < 2) {
                unsigned int target = (unsigned)(s + 1) * 16u;
                const unsigned int* c = ctrs + tid * 32;
                unsigned int v;
                do {
                    asm volatile("ld.acquire.gpu.global.u32 %0, [%1];"
                                 : "=r"(v) : "l"(c) : "memory");
                } while (v < target);
            }
            __syncthreads();   // (G)
        }
    }
}

// ---------------- KAN prep: cubic B-spline basis on efficient-kan extended grid ----------------
__device__ __forceinline__ void bspline8(float x, float* bs) {
    const float hstep = 2.0f / 5.0f;
    float g[12];
#pragma unroll
    for (int m = 0; m < 12; m++) g[m] = (float)(m - 3) * hstep - 1.0f;
    float b[11];
#pragma unroll
    for (int m = 0; m < 11; m++) b[m] = (x >= g[m] && x < g[m + 1]) ? 1.f : 0.f;
#pragma unroll
    for (int k = 1; k <= 3; k++) {
#pragma unroll
        for (int m = 0; m < 11 - k; m++) {
            b[m] = (x - g[m]) / (g[m + k] - g[m]) * b[m]
                 + (g[m + k + 1] - x) / (g[m + k + 1] - g[m + 1]) * b[m + 1];
        }
    }
#pragma unroll
    for (int m = 0; m < 8; m++) bs[m] = b[m];
}

// U[n] = [ silu(x[n,:]) | bases(x[n,:])... ] width = 9*inw
__global__ void prep_U_kernel(const float* __restrict__ X, float* __restrict__ U, int inw) {
    int idx = blockIdx.x * blockDim.x + threadIdx.x;
    int total = LSEQ * inw;
    if (idx >= total) return;
    int n = idx / inw, i = idx - n * inw;
    float x = X[idx];
    int uw = inw * 9;
    U[(size_t)n * uw + i] = x / (1.f + expf(-x));
    float bs[8];
    bspline8(x, bs);
    float4* d4 = (float4*)(U + (size_t)n * uw + inw + (size_t)i * 8);
    d4[0] = make_float4(bs[0], bs[1], bs[2], bs[3]);
    d4[1] = make_float4(bs[4], bs[5], bs[6], bs[7]);
}

// V[o] = [ base_w[o,:] | spline_w[o,:,:]*scaler[o,:] ]
__global__ void prep_V_kernel(const float* __restrict__ bw, const float* __restrict__ sw,
                              const float* __restrict__ sc, float* __restrict__ V, int inw) {
    int idx = blockIdx.x * blockDim.x + threadIdx.x;
    int total = HDIM * inw;
    if (idx >= total) return;
    int o = idx / inw, i = idx - o * inw;
    int uw = inw * 9;
    V[(size_t)o * uw + i] = bw[idx];
    float s = sc[idx];
    const float* swp = sw + (size_t)idx * 8;
    float4* d4 = (float4*)(V + (size_t)o * uw + inw + (size_t)i * 8);
    d4[0] = make_float4(swp[0] * s, swp[1] * s, swp[2] * s, swp[3] * s);
    d4[1] = make_float4(swp[4] * s, swp[5] * s, swp[6] * s, swp[7] * s);
}

// ---------------- y[o] = sum_n a2[n,o] * p[n] ----------------
__global__ void final_kernel(const float* __restrict__ p, float* __restrict__ y) {
    __shared__ float red[256];
    int o = blockIdx.x * 64 + (threadIdx.x & 63);
    int part = threadIdx.x >> 6;
    float acc = 0.f;
    for (int n = part; n < LSEQ; n += 4)
        acc += d_a2[(size_t)n * HDIM + o] * p[n];
    red[threadIdx.x] = acc;
    __syncthreads();
    if (part == 0)
        y[o] = red[threadIdx.x] + red[threadIdx.x + 64]
             + red[threadIdx.x + 128] + red[threadIdx.x + 192];
}

// ---------------- launch ----------------
extern "C" void kernel_launch(void* const* d_in, const int* in_sizes, int n_in,
                              void* d_out, int out_size) {
    const float* h    = (const float*)d_in[0];
    const float* p    = (const float*)d_in[1];
    const float* wihf = (const float*)d_in[2];
    const float* whhf = (const float*)d_in[3];
    const float* bihf = (const float*)d_in[4];
    const float* bhhf = (const float*)d_in[5];
    const float* wihb = (const float*)d_in[6];
    const float* whhb = (const float*)d_in[7];
    const float* bihb = (const float*)d_in[8];
    const float* bhhb = (const float*)d_in[9];
    const float* bw1  = (const float*)d_in[10];
    const float* sw1  = (const float*)d_in[11];
    const float* sc1  = (const float*)d_in[12];
    const float* bw2  = (const float*)d_in[13];
    const float* sw2  = (const float*)d_in[14];
    const float* sc2  = (const float*)d_in[15];

    float* out = (float*)d_out;
    float* y  = out;           // (512,)
    float* a1 = out + 512;     // (4096, 512)

    float *gi0, *oc, *u1, *v1, *u2, *v2, *a2;
    cudaGetSymbolAddress((void**)&gi0, d_gi);
    cudaGetSymbolAddress((void**)&oc,  d_outcat);
    cudaGetSymbolAddress((void**)&u1,  d_U1);
    cudaGetSymbolAddress((void**)&v1,  d_V1);
    cudaGetSymbolAddress((void**)&u2,  d_U2);
    cudaGetSymbolAddress((void**)&v2,  d_V2);
    cudaGetSymbolAddress((void**)&a2,  d_a2);
    float* gi1 = gi0 + (size_t)LSEQ * 1536;

    init_kernel<<<2, 1024>>>();

    // input-gate GEMMs: gi = h @ w_ih^T + b_ih   (4096 x 1536, K=512)
    sgemm_kernel<<<dim3(1536 / 128, LSEQ / 128), 256>>>(h, wihf, bihf, gi0, LSEQ, 1536, 512, 0);
    sgemm_kernel<<<dim3(1536 / 128, LSEQ / 128), 256>>>(h, wihb, bihb, gi1, LSEQ, 1536, 512, 0);

    // persistent bidirectional recurrence
    gru_kernel<<<2 * GCTAS, GTH>>>(whhf, bhhf, whhb, bhhb);

    // KAN layer 1: a1 = relu(U1 @ V1^T), U1 = [silu | bases] of outcat (width 9216)
    prep_V_kernel<<<(HDIM * 1024 + 255) / 256, 256>>>(bw1, sw1, sc1, v1, 1024);
    prep_U_kernel<<<(LSEQ * 1024 + 255) / 256, 256>>>(oc, u1, 1024);
    sgemm_kernel<<<dim3(HDIM / 128, LSEQ / 128), 256>>>(u1, v1, nullptr, a1, LSEQ, HDIM, 9216, 1);

    // KAN layer 2: a2 = sigmoid(U2 @ V2^T), width 4608
    prep_V_kernel<<<(HDIM * 512 + 255) / 256, 256>>>(bw2, sw2, sc2, v2, 512);
    prep_U_kernel<<<(LSEQ * 512 + 255) / 256, 256>>>(a1, u2, 512);
    sgemm_kernel<<<dim3(HDIM / 128, LSEQ / 128), 256>>>(u2, v2, nullptr, a2, LSEQ, HDIM, 4608, 2);

    // y = a2^T @ p
    final_kernel<<<8, 256>>>(p, y);
}